// round 7
// baseline (speedup 1.0000x reference)
#include <cuda_runtime.h>

// out[b,d,t] = T*x[b,d,t] - 2 * sum_{s ≡ t (mod 2)} x[b,d,s],  T = 1024.
// (Dirichlet-kernel collapse of the rfft -> cos/sin GEMM reference; see R1.)
//
// R6: warp-per-row, two-pass over the row to cut register pressure.
// Pass 1 streams the row and accumulates (even,odd) sums; pass 2 re-reads it
// (L1/L2 hit) and stores T*x - 2*sum. __launch_bounds__(256,8) pins regs<=32
// so all 1024 CTAs are resident in a single wave (was 2 waves at 48 regs).

#define ROW_LEN      1024
#define THREADS      256          // 8 warps -> 8 rows per block
#define VEC_PER_LANE 8            // 8 float4 = 32 floats per lane

__global__ __launch_bounds__(THREADS, 8)
void season_block_46428596469890_kernel(const float* __restrict__ x,
                                        float* __restrict__ out) {
    const int lane = threadIdx.x & 31;
    const int warp = threadIdx.x >> 5;
    const long long row = (long long)blockIdx.x * 8 + warp;

    const float4* __restrict__ xr =
        reinterpret_cast<const float4*>(x + row * ROW_LEN);
    float4* __restrict__ outr = reinterpret_cast<float4*>(out + row * ROW_LEN);

    // Pass 1: accumulate even/odd sums. Element index of v.x is 4*(lane+32j):
    // .x/.z always even, .y/.w always odd.
    float esum = 0.0f, osum = 0.0f;
    #pragma unroll
    for (int j = 0; j < VEC_PER_LANE; j++) {
        float4 v = xr[lane + 32 * j];
        esum += v.x + v.z;
        osum += v.y + v.w;
    }

    // Warp-only reduction; every lane ends with the full-row sums.
    #pragma unroll
    for (int off = 16; off > 0; off >>= 1) {
        esum += __shfl_xor_sync(0xffffffffu, esum, off);
        osum += __shfl_xor_sync(0xffffffffu, osum, off);
    }

    const float E2 = 2.0f * esum;
    const float O2 = 2.0f * osum;
    const float T  = (float)ROW_LEN;

    // Pass 2: re-read (L1/L2 resident) and write the fused result.
    #pragma unroll
    for (int j = 0; j < VEC_PER_LANE; j++) {
        float4 v = xr[lane + 32 * j];
        float4 r;
        r.x = fmaf(T, v.x, -E2);
        r.y = fmaf(T, v.y, -O2);
        r.z = fmaf(T, v.z, -E2);
        r.w = fmaf(T, v.w, -O2);
        outr[lane + 32 * j] = r;
    }
}

extern "C" void kernel_launch(void* const* d_in, const int* in_sizes, int n_in,
                              void* d_out, int out_size) {
    const float* x = (const float*)d_in[0];
    float* out = (float*)d_out;
    const int n_rows = in_sizes[0] / ROW_LEN;     // 8192
    season_block_46428596469890_kernel<<<n_rows / 8, THREADS>>>(x, out);
}

// round 8
// speedup vs baseline: 1.4060x; 1.4060x over previous
#include <cuda_runtime.h>

// out[b,d,t] = T*x[b,d,t] - 2 * sum_{s ≡ t (mod 2)} x[b,d,s],  T = 1024.
// (Dirichlet-kernel collapse of the rfft -> cos/sin GEMM reference; see R1.)
//
// R7: R5 (warp-per-row, register-resident single pass, shuffle-only reduce)
// + streaming stores (st.global.cs). Output lines are evict-first in L2:
// protects the L2-resident input from write-allocate displacement and
// smooths the DRAM write drain. R6 post-mortem showed occupancy is NOT the
// lever (R1 occ 84% = 13.0us, R6 occ 64% = 15.1us, R5 occ 46% = 10.9us);
// the register-resident single-pass structure is kept verbatim.

#define ROW_LEN      1024
#define THREADS      256          // 8 warps -> 8 rows per block
#define VEC_PER_LANE 8            // 8 float4 = 32 floats per lane

__global__ __launch_bounds__(THREADS)
void season_block_46428596469890_kernel(const float* __restrict__ x,
                                        float* __restrict__ out) {
    const int lane = threadIdx.x & 31;
    const int warp = threadIdx.x >> 5;
    const long long row = (long long)blockIdx.x * 8 + warp;

    const float4* __restrict__ xr =
        reinterpret_cast<const float4*>(x + row * ROW_LEN);
    float4* __restrict__ outr = reinterpret_cast<float4*>(out + row * ROW_LEN);

    // Front-batched independent loads: MLP = 8 per lane (LDG.128).
    float4 v[VEC_PER_LANE];
    #pragma unroll
    for (int j = 0; j < VEC_PER_LANE; j++)
        v[j] = xr[lane + 32 * j];

    // Element index of v[j].x is 4*(lane + 32j): .x/.z always even, .y/.w odd.
    float esum = 0.0f, osum = 0.0f;
    #pragma unroll
    for (int j = 0; j < VEC_PER_LANE; j++) {
        esum += v[j].x + v[j].z;
        osum += v[j].y + v[j].w;
    }

    // Warp-only reduction; every lane ends with the full-row sums.
    #pragma unroll
    for (int off = 16; off > 0; off >>= 1) {
        esum += __shfl_xor_sync(0xffffffffu, esum, off);
        osum += __shfl_xor_sync(0xffffffffu, osum, off);
    }

    const float E2 = 2.0f * esum;
    const float O2 = 2.0f * osum;
    const float T  = (float)ROW_LEN;

    // Streaming stores: evict-first, straight from registers.
    #pragma unroll
    for (int j = 0; j < VEC_PER_LANE; j++) {
        float4 r;
        r.x = fmaf(T, v[j].x, -E2);
        r.y = fmaf(T, v[j].y, -O2);
        r.z = fmaf(T, v[j].z, -E2);
        r.w = fmaf(T, v[j].w, -O2);
        __stcs(&outr[lane + 32 * j], r);
    }
}

extern "C" void kernel_launch(void* const* d_in, const int* in_sizes, int n_in,
                              void* d_out, int out_size) {
    const float* x = (const float*)d_in[0];
    float* out = (float*)d_out;
    const int n_rows = in_sizes[0] / ROW_LEN;     // 8192
    season_block_46428596469890_kernel<<<n_rows / 8, THREADS>>>(x, out);
}